// round 4
// baseline (speedup 1.0000x reference)
#include <cuda_runtime.h>

#define LATENT   16
#define NREP     10
#define NSTEPS   10
#define NLIB     169
#define DT_F     0.01f

// ---- packed f32x2 helpers (sm_100a family) ----
__device__ __forceinline__ unsigned long long pack2(float lo, float hi) {
    unsigned long long r;
    asm("mov.b64 %0, {%1, %2};" : "=l"(r) : "f"(lo), "f"(hi));
    return r;
}
__device__ __forceinline__ unsigned long long fma2(unsigned long long a,
                                                   unsigned long long b,
                                                   unsigned long long c) {
    unsigned long long d;
    asm("fma.rn.f32x2 %0, %1, %2, %3;" : "=l"(d) : "l"(a), "l"(b), "l"(c));
    return d;
}
__device__ __forceinline__ void unpack2(unsigned long long v, float& lo, float& hi) {
    asm("mov.b64 {%0, %1}, %2;" : "=f"(lo), "=f"(hi) : "l"(v));
}

// One thread per (sample, replicate). Identical structure to the proven
// 78-reg R1 kernel, but coefficient rows are read as 4x LDS.128 (ulonglong2)
// instead of 8x LDS.64 — halves L1 wavefronts, which was the 91% binder.
__global__ __launch_bounds__(256)
void sindy_shred_kernel(const float* __restrict__ h_t,
                        const float* __restrict__ coeff,
                        const float* __restrict__ mask,
                        float* __restrict__ out,
                        int n_total)
{
    __shared__ __align__(16) unsigned long long C2[NLIB * 8];

    const int r = blockIdx.y;
    {
        const float* cr = coeff + (size_t)r * NLIB * LATENT;
        const float* mr = mask  + (size_t)r * NLIB * LATENT;
        for (int idx = threadIdx.x; idx < NLIB * 8; idx += blockDim.x) {
            int base = idx * 2;
            C2[idx] = pack2(cr[base] * mr[base], cr[base + 1] * mr[base + 1]);
        }
    }
    __syncthreads();

    const int n = blockIdx.x * blockDim.x + threadIdx.x;
    if (n >= n_total) return;

    float z[LATENT];
    {
        const float4* hin = reinterpret_cast<const float4*>(h_t + (size_t)n * LATENT);
        #pragma unroll
        for (int k = 0; k < 4; k++) {
            float4 v = hin[k];
            z[4*k + 0] = v.x; z[4*k + 1] = v.y;
            z[4*k + 2] = v.z; z[4*k + 3] = v.w;
        }
    }

    const ulonglong2* __restrict__ C2v = reinterpret_cast<const ulonglong2*>(C2);

    for (int step = 0; step < NSTEPS; step++) {
        unsigned long long acc[8];
        // Row 0: constant term (theta = 1) -> accumulators start at row 0.
        #pragma unroll
        for (int q = 0; q < 4; q++) {
            ulonglong2 c = C2v[q];
            acc[2*q]   = c.x;
            acc[2*q+1] = c.y;
        }

        // Row update with theta t at row l: 4x LDS.128 + 8x FFMA2.
        #define ROW_OP(l, t) do {                                              \
            unsigned long long tp = pack2((t), (t));                           \
            _Pragma("unroll")                                                  \
            for (int q = 0; q < 4; q++) {                                      \
                ulonglong2 c = C2v[(l) * 4 + q];                               \
                acc[2*q]   = fma2(tp, c.x, acc[2*q]);                          \
                acc[2*q+1] = fma2(tp, c.y, acc[2*q+1]);                        \
            }                                                                  \
        } while (0)

        // Linear terms: rows 1..16
        #pragma unroll
        for (int i = 0; i < LATENT; i++) {
            ROW_OP(1 + i, z[i]);
        }

        // Quadratic terms: rows 17..152, triu(i<=j) row-major
        {
            int l = 1 + LATENT;
            for (int i = 0; i < LATENT; i++) {
                float zi = z[i];
                for (int j = i; j < LATENT; j++) {
                    ROW_OP(l, zi * z[j]);
                    l++;
                }
            }
        }

        // Sine terms: rows 153..168
        #pragma unroll
        for (int i = 0; i < LATENT; i++) {
            ROW_OP(153 + i, __sinf(z[i]));
        }
        #undef ROW_OP

        // Euler update: z += dz * DT (FFMA with immediate multiplier)
        #pragma unroll
        for (int k = 0; k < 8; k++) {
            float a, b;
            unpack2(acc[k], a, b);
            z[2*k + 0] = fmaf(a, DT_F, z[2*k + 0]);
            z[2*k + 1] = fmaf(b, DT_F, z[2*k + 1]);
        }
    }

    // Store out[n][r][0:16]
    {
        float4* po = reinterpret_cast<float4*>(out + ((size_t)n * NREP + r) * LATENT);
        #pragma unroll
        for (int k = 0; k < 4; k++) {
            po[k] = make_float4(z[4*k + 0], z[4*k + 1], z[4*k + 2], z[4*k + 3]);
        }
    }
}

extern "C" void kernel_launch(void* const* d_in, const int* in_sizes, int n_in,
                              void* d_out, int out_size)
{
    const float* h_t   = (const float*)d_in[0];   // [50000, 16]
    const float* coeff = (const float*)d_in[1];   // [10, 169, 16]
    const float* mask  = (const float*)d_in[2];   // [10, 169, 16]
    float* out = (float*)d_out;                   // [50000, 10, 16]

    int n_total = in_sizes[0] / LATENT;
    dim3 grid((unsigned)((n_total + 255) / 256), NREP, 1);
    sindy_shred_kernel<<<grid, 256>>>(h_t, coeff, mask, out, n_total);
}

// round 5
// speedup vs baseline: 2.2122x; 2.2122x over previous
#include <cuda_runtime.h>

#define LATENT   16
#define NREP     10
#define NSTEPS   10
#define NLIB     169
#define DT_F     0.01f

// ---- packed f32x2 helpers (sm_100a family) ----
__device__ __forceinline__ unsigned long long pack2(float lo, float hi) {
    unsigned long long r;
    asm("mov.b64 %0, {%1, %2};" : "=l"(r) : "f"(lo), "f"(hi));
    return r;
}
__device__ __forceinline__ unsigned long long fma2(unsigned long long a,
                                                   unsigned long long b,
                                                   unsigned long long c) {
    unsigned long long d;
    asm("fma.rn.f32x2 %0, %1, %2, %3;" : "=l"(d) : "l"(a), "l"(b), "l"(c));
    return d;
}
__device__ __forceinline__ void unpack2(unsigned long long v, float& lo, float& hi) {
    asm("mov.b64 {%0, %1}, %2;" : "=f"(lo), "=f"(hi) : "l"(v));
}

// TWO samples per thread, SCALAR LDS.64 row loads (R1's proven codegen shape:
// no vector LDS -> no register-alignment pressure). One coefficient row load
// now feeds 2 samples (16 FFMA2), halving L1 wavefronts per sample — the 91%
// binder in R1. 128 threads/block + launch_bounds(128,1) gives ptxas up to
// 255 regs so the doubled state cannot spill (R2's failure mode).
__global__ __launch_bounds__(128, 1)
void sindy_shred_kernel(const float* __restrict__ h_t,
                        const float* __restrict__ coeff,
                        const float* __restrict__ mask,
                        float* __restrict__ out,
                        int n_total)
{
    __shared__ __align__(16) unsigned long long C2[NLIB * 8];

    const int r = blockIdx.y;
    {
        const float* cr = coeff + (size_t)r * NLIB * LATENT;
        const float* mr = mask  + (size_t)r * NLIB * LATENT;
        for (int idx = threadIdx.x; idx < NLIB * 8; idx += blockDim.x) {
            int base = idx * 2;
            C2[idx] = pack2(cr[base] * mr[base], cr[base + 1] * mr[base + 1]);
        }
    }
    __syncthreads();

    const int n0 = blockIdx.x * 256 + threadIdx.x;   // 2 samples/thread, 128 threads
    const int n1 = n0 + 128;
    const bool v0 = (n0 < n_total);
    const bool v1 = (n1 < n_total);
    if (!v0) return;

    float z0[LATENT], z1[LATENT];
    {
        const float4* p0 = reinterpret_cast<const float4*>(h_t + (size_t)n0 * LATENT);
        #pragma unroll
        for (int k = 0; k < 4; k++) {
            float4 v = p0[k];
            z0[4*k+0] = v.x; z0[4*k+1] = v.y; z0[4*k+2] = v.z; z0[4*k+3] = v.w;
        }
        if (v1) {
            const float4* p1 = reinterpret_cast<const float4*>(h_t + (size_t)n1 * LATENT);
            #pragma unroll
            for (int k = 0; k < 4; k++) {
                float4 v = p1[k];
                z1[4*k+0] = v.x; z1[4*k+1] = v.y; z1[4*k+2] = v.z; z1[4*k+3] = v.w;
            }
        } else {
            #pragma unroll
            for (int k = 0; k < LATENT; k++) z1[k] = 0.0f;
        }
    }

    for (int step = 0; step < NSTEPS; step++) {
        unsigned long long acc0[8], acc1[8];
        // Row 0: constant term (theta = 1).
        #pragma unroll
        for (int k = 0; k < 8; k++) {
            unsigned long long c = C2[k];
            acc0[k] = c;
            acc1[k] = c;
        }

        // Row update: 8 scalar LDS.64 + 16 FFMA2 (8 per sample).
        #define ROW_OP(l, t0, t1) do {                                         \
            unsigned long long p0 = pack2((t0), (t0));                         \
            unsigned long long p1 = pack2((t1), (t1));                         \
            const unsigned long long* row_ = &C2[(l) * 8];                     \
            _Pragma("unroll")                                                  \
            for (int k = 0; k < 8; k++) {                                      \
                unsigned long long c = row_[k];                                \
                acc0[k] = fma2(p0, c, acc0[k]);                                \
                acc1[k] = fma2(p1, c, acc1[k]);                                \
            }                                                                  \
        } while (0)

        // Linear terms: rows 1..16
        #pragma unroll 4
        for (int i = 0; i < LATENT; i++) {
            ROW_OP(1 + i, z0[i], z1[i]);
        }

        // Quadratic terms: rows 17..152, triu(i<=j) row-major (runtime loops
        // on purpose — full unroll here spilled in R2).
        {
            int l = 1 + LATENT;
            for (int i = 0; i < LATENT; i++) {
                float a = z0[i], b = z1[i];
                for (int j = i; j < LATENT; j++) {
                    ROW_OP(l, a * z0[j], b * z1[j]);
                    l++;
                }
            }
        }

        // Sine terms: rows 153..168
        #pragma unroll 4
        for (int i = 0; i < LATENT; i++) {
            ROW_OP(153 + i, __sinf(z0[i]), __sinf(z1[i]));
        }
        #undef ROW_OP

        // Euler update: z += dz * DT (FFMA-imm)
        #pragma unroll
        for (int k = 0; k < 8; k++) {
            float a, b;
            unpack2(acc0[k], a, b);
            z0[2*k+0] = fmaf(a, DT_F, z0[2*k+0]);
            z0[2*k+1] = fmaf(b, DT_F, z0[2*k+1]);
            unpack2(acc1[k], a, b);
            z1[2*k+0] = fmaf(a, DT_F, z1[2*k+0]);
            z1[2*k+1] = fmaf(b, DT_F, z1[2*k+1]);
        }
    }

    // Store out[n][r][0:16]
    {
        float4* po = reinterpret_cast<float4*>(out + ((size_t)n0 * NREP + r) * LATENT);
        #pragma unroll
        for (int k = 0; k < 4; k++)
            po[k] = make_float4(z0[4*k+0], z0[4*k+1], z0[4*k+2], z0[4*k+3]);
        if (v1) {
            float4* p1 = reinterpret_cast<float4*>(out + ((size_t)n1 * NREP + r) * LATENT);
            #pragma unroll
            for (int k = 0; k < 4; k++)
                p1[k] = make_float4(z1[4*k+0], z1[4*k+1], z1[4*k+2], z1[4*k+3]);
        }
    }
}

extern "C" void kernel_launch(void* const* d_in, const int* in_sizes, int n_in,
                              void* d_out, int out_size)
{
    const float* h_t   = (const float*)d_in[0];   // [50000, 16]
    const float* coeff = (const float*)d_in[1];   // [10, 169, 16]
    const float* mask  = (const float*)d_in[2];   // [10, 169, 16]
    float* out = (float*)d_out;                   // [50000, 10, 16]

    int n_total = in_sizes[0] / LATENT;
    int blocks_x = (n_total + 255) / 256;         // 256 samples per block
    dim3 grid((unsigned)blocks_x, NREP, 1);
    sindy_shred_kernel<<<grid, 128>>>(h_t, coeff, mask, out, n_total);
}

// round 6
// speedup vs baseline: 2.2450x; 1.0148x over previous
#include <cuda_runtime.h>

#define LATENT   16
#define NREP     10
#define NSTEPS   10
#define NLIB     169
#define DT_F     0.01f

// ---- packed f32x2 helpers (sm_100a family) ----
__device__ __forceinline__ unsigned long long pack2(float lo, float hi) {
    unsigned long long r;
    asm("mov.b64 %0, {%1, %2};" : "=l"(r) : "f"(lo), "f"(hi));
    return r;
}
__device__ __forceinline__ unsigned long long fma2(unsigned long long a,
                                                   unsigned long long b,
                                                   unsigned long long c) {
    unsigned long long d;
    asm("fma.rn.f32x2 %0, %1, %2, %3;" : "=l"(d) : "l"(a), "l"(b), "l"(c));
    return d;
}
__device__ __forceinline__ void unpack2(unsigned long long v, float& lo, float& hi) {
    asm("mov.b64 {%0, %1}, %2;" : "=f"(lo), "=f"(hi) : "l"(v));
}

// THREE samples per thread, scalar LDS.64 row loads (proven no-spill codegen
// shape). One coefficient row load now feeds 3 samples (24 FFMA2), cutting L1
// wavefronts per sample to 1/3 of R1 — LDS time ~250us < FMA pipe ~420us, so
// the fma pipe becomes the binder. launch_bounds(128,1) keeps the 255-reg
// ceiling so the tripled state stays in registers.
__global__ __launch_bounds__(128, 1)
void sindy_shred_kernel(const float* __restrict__ h_t,
                        const float* __restrict__ coeff,
                        const float* __restrict__ mask,
                        float* __restrict__ out,
                        int n_total)
{
    __shared__ __align__(16) unsigned long long C2[NLIB * 8];

    const int r = blockIdx.y;
    {
        const float* cr = coeff + (size_t)r * NLIB * LATENT;
        const float* mr = mask  + (size_t)r * NLIB * LATENT;
        for (int idx = threadIdx.x; idx < NLIB * 8; idx += blockDim.x) {
            int base = idx * 2;
            C2[idx] = pack2(cr[base] * mr[base], cr[base + 1] * mr[base + 1]);
        }
    }
    __syncthreads();

    const int n0 = blockIdx.x * 384 + threadIdx.x;   // 3 samples/thread
    const int n1 = n0 + 128;
    const int n2 = n0 + 256;
    const bool v1 = (n1 < n_total);
    const bool v2 = (n2 < n_total);
    if (n0 >= n_total) return;

    float z0[LATENT], z1[LATENT], z2[LATENT];
    {
        const float4* p0 = reinterpret_cast<const float4*>(h_t + (size_t)n0 * LATENT);
        #pragma unroll
        for (int k = 0; k < 4; k++) {
            float4 v = p0[k];
            z0[4*k+0] = v.x; z0[4*k+1] = v.y; z0[4*k+2] = v.z; z0[4*k+3] = v.w;
        }
        if (v1) {
            const float4* p1 = reinterpret_cast<const float4*>(h_t + (size_t)n1 * LATENT);
            #pragma unroll
            for (int k = 0; k < 4; k++) {
                float4 v = p1[k];
                z1[4*k+0] = v.x; z1[4*k+1] = v.y; z1[4*k+2] = v.z; z1[4*k+3] = v.w;
            }
        } else {
            #pragma unroll
            for (int k = 0; k < LATENT; k++) z1[k] = 0.0f;
        }
        if (v2) {
            const float4* p2 = reinterpret_cast<const float4*>(h_t + (size_t)n2 * LATENT);
            #pragma unroll
            for (int k = 0; k < 4; k++) {
                float4 v = p2[k];
                z2[4*k+0] = v.x; z2[4*k+1] = v.y; z2[4*k+2] = v.z; z2[4*k+3] = v.w;
            }
        } else {
            #pragma unroll
            for (int k = 0; k < LATENT; k++) z2[k] = 0.0f;
        }
    }

    for (int step = 0; step < NSTEPS; step++) {
        unsigned long long acc0[8], acc1[8], acc2[8];
        // Row 0: constant term (theta = 1).
        #pragma unroll
        for (int k = 0; k < 8; k++) {
            unsigned long long c = C2[k];
            acc0[k] = c; acc1[k] = c; acc2[k] = c;
        }

        // Row update: 8 scalar LDS.64 + 24 FFMA2 (8 per sample).
        #define ROW_OP(l, t0, t1, t2) do {                                     \
            unsigned long long p0 = pack2((t0), (t0));                         \
            unsigned long long p1 = pack2((t1), (t1));                         \
            unsigned long long p2 = pack2((t2), (t2));                         \
            const unsigned long long* row_ = &C2[(l) * 8];                     \
            _Pragma("unroll")                                                  \
            for (int k = 0; k < 8; k++) {                                      \
                unsigned long long c = row_[k];                                \
                acc0[k] = fma2(p0, c, acc0[k]);                                \
                acc1[k] = fma2(p1, c, acc1[k]);                                \
                acc2[k] = fma2(p2, c, acc2[k]);                                \
            }                                                                  \
        } while (0)

        // Linear terms: rows 1..16
        #pragma unroll 4
        for (int i = 0; i < LATENT; i++) {
            ROW_OP(1 + i, z0[i], z1[i], z2[i]);
        }

        // Quadratic terms: rows 17..152, triu(i<=j) row-major (runtime loops
        // on purpose — full unroll here spilled in R2).
        {
            int l = 1 + LATENT;
            for (int i = 0; i < LATENT; i++) {
                float a = z0[i], b = z1[i], c3 = z2[i];
                for (int j = i; j < LATENT; j++) {
                    ROW_OP(l, a * z0[j], b * z1[j], c3 * z2[j]);
                    l++;
                }
            }
        }

        // Sine terms: rows 153..168
        #pragma unroll 4
        for (int i = 0; i < LATENT; i++) {
            ROW_OP(153 + i, __sinf(z0[i]), __sinf(z1[i]), __sinf(z2[i]));
        }
        #undef ROW_OP

        // Euler update: z += dz * DT (FFMA-imm)
        #pragma unroll
        for (int k = 0; k < 8; k++) {
            float a, b;
            unpack2(acc0[k], a, b);
            z0[2*k+0] = fmaf(a, DT_F, z0[2*k+0]);
            z0[2*k+1] = fmaf(b, DT_F, z0[2*k+1]);
            unpack2(acc1[k], a, b);
            z1[2*k+0] = fmaf(a, DT_F, z1[2*k+0]);
            z1[2*k+1] = fmaf(b, DT_F, z1[2*k+1]);
            unpack2(acc2[k], a, b);
            z2[2*k+0] = fmaf(a, DT_F, z2[2*k+0]);
            z2[2*k+1] = fmaf(b, DT_F, z2[2*k+1]);
        }
    }

    // Store out[n][r][0:16]
    {
        float4* po = reinterpret_cast<float4*>(out + ((size_t)n0 * NREP + r) * LATENT);
        #pragma unroll
        for (int k = 0; k < 4; k++)
            po[k] = make_float4(z0[4*k+0], z0[4*k+1], z0[4*k+2], z0[4*k+3]);
        if (v1) {
            float4* p1 = reinterpret_cast<float4*>(out + ((size_t)n1 * NREP + r) * LATENT);
            #pragma unroll
            for (int k = 0; k < 4; k++)
                p1[k] = make_float4(z1[4*k+0], z1[4*k+1], z1[4*k+2], z1[4*k+3]);
        }
        if (v2) {
            float4* p2 = reinterpret_cast<float4*>(out + ((size_t)n2 * NREP + r) * LATENT);
            #pragma unroll
            for (int k = 0; k < 4; k++)
                p2[k] = make_float4(z2[4*k+0], z2[4*k+1], z2[4*k+2], z2[4*k+3]);
        }
    }
}

extern "C" void kernel_launch(void* const* d_in, const int* in_sizes, int n_in,
                              void* d_out, int out_size)
{
    const float* h_t   = (const float*)d_in[0];   // [50000, 16]
    const float* coeff = (const float*)d_in[1];   // [10, 169, 16]
    const float* mask  = (const float*)d_in[2];   // [10, 169, 16]
    float* out = (float*)d_out;                   // [50000, 10, 16]

    int n_total = in_sizes[0] / LATENT;
    int blocks_x = (n_total + 383) / 384;         // 384 samples per block
    dim3 grid((unsigned)blocks_x, NREP, 1);
    sindy_shred_kernel<<<grid, 128>>>(h_t, coeff, mask, out, n_total);
}

// round 8
// speedup vs baseline: 2.8960x; 1.2900x over previous
#include <cuda_runtime.h>
#include <cuda_bf16.h>

#define LATENT   16
#define NREP     10
#define NSTEPS   10
#define NLIB     169
#define DT_F     0.01f

// pack two u32 -> u64 (register pair; no real instruction)
__device__ __forceinline__ unsigned long long pack2u(unsigned lo, unsigned hi) {
    unsigned long long r;
    asm("mov.b64 %0, {%1, %2};" : "=l"(r) : "r"(lo), "r"(hi));
    return r;
}
// bf16x2 fused multiply-add (HFMA2.BF16_V2, fma pipe, rt=2, 2 MACs/instr)
__device__ __forceinline__ unsigned hfma2(unsigned a, unsigned b, unsigned c) {
    unsigned d;
    asm("fma.rn.bf16x2 %0, %1, %2, %3;" : "=r"(d) : "r"(a), "r"(b), "r"(c));
    return d;
}
// pack (lo, hi) f32 -> bf16x2  (PTX: cvt d, a, b puts a in the HIGH half)
#define CVT2(dst, lo, hi) \
    asm("cvt.rn.bf16x2.f32 %0, %1, %2;" : "=r"(dst) : "f"(hi), "f"(lo))

// bf16 halves of a bf16x2 -> f32 (bit tricks: bf16 bits are the top 16 of f32)
__device__ __forceinline__ float bf16lo_f(unsigned v) {
    return __uint_as_float(v << 16);
}
__device__ __forceinline__ float bf16hi_f(unsigned v) {
    return __uint_as_float(v & 0xFFFF0000u);
}

// THREE samples per thread. Contraction in bf16x2 HFMA2:
//  - coefficient row = 16 bf16 = 32 B = 4 scalar LDS.64 (half of R5's LDS count)
//  - accumulators are bf16x2 (8 u32/sample) -> much lower register pressure
//  - theta built in fp32, one CVT per row per sample
// launch_bounds(128,3): >=3 blocks/SM (12 warps) with a 170-reg no-spill ceiling.
__global__ __launch_bounds__(128, 3)
void sindy_shred_kernel(const float* __restrict__ h_t,
                        const float* __restrict__ coeff,
                        const float* __restrict__ mask,
                        float* __restrict__ out,
                        int n_total)
{
    // C4[row*4 + m] = u64 holding coeffs d=4m..4m+3 as two bf16x2 pairs
    __shared__ __align__(16) unsigned long long C4[NLIB * 4];

    const int r = blockIdx.y;
    {
        const float* cr = coeff + (size_t)r * NLIB * LATENT;
        const float* mr = mask  + (size_t)r * NLIB * LATENT;
        for (int idx = threadIdx.x; idx < NLIB * 4; idx += blockDim.x) {
            int base = idx * 4;   // row*16 + m*4
            float c0 = cr[base + 0] * mr[base + 0];
            float c1 = cr[base + 1] * mr[base + 1];
            float c2 = cr[base + 2] * mr[base + 2];
            float c3 = cr[base + 3] * mr[base + 3];
            unsigned plo, phi;
            CVT2(plo, c0, c1);
            CVT2(phi, c2, c3);
            C4[idx] = pack2u(plo, phi);
        }
    }
    __syncthreads();

    const int n0 = blockIdx.x * 384 + threadIdx.x;   // 3 samples/thread
    const int n1 = n0 + 128;
    const int n2 = n0 + 256;
    const bool v1 = (n1 < n_total);
    const bool v2 = (n2 < n_total);
    if (n0 >= n_total) return;

    float z0[LATENT], z1[LATENT], z2[LATENT];
    {
        const float4* p0 = reinterpret_cast<const float4*>(h_t + (size_t)n0 * LATENT);
        #pragma unroll
        for (int k = 0; k < 4; k++) {
            float4 v = p0[k];
            z0[4*k+0] = v.x; z0[4*k+1] = v.y; z0[4*k+2] = v.z; z0[4*k+3] = v.w;
        }
        if (v1) {
            const float4* p1 = reinterpret_cast<const float4*>(h_t + (size_t)n1 * LATENT);
            #pragma unroll
            for (int k = 0; k < 4; k++) {
                float4 v = p1[k];
                z1[4*k+0] = v.x; z1[4*k+1] = v.y; z1[4*k+2] = v.z; z1[4*k+3] = v.w;
            }
        } else {
            #pragma unroll
            for (int k = 0; k < LATENT; k++) z1[k] = 0.0f;
        }
        if (v2) {
            const float4* p2 = reinterpret_cast<const float4*>(h_t + (size_t)n2 * LATENT);
            #pragma unroll
            for (int k = 0; k < 4; k++) {
                float4 v = p2[k];
                z2[4*k+0] = v.x; z2[4*k+1] = v.y; z2[4*k+2] = v.z; z2[4*k+3] = v.w;
            }
        } else {
            #pragma unroll
            for (int k = 0; k < LATENT; k++) z2[k] = 0.0f;
        }
    }

    for (int step = 0; step < NSTEPS; step++) {
        // acc{S}[q] = bf16x2 (dz_2q, dz_2q+1) for sample S
        unsigned acc0[8], acc1[8], acc2[8];
        // Row 0: constant term (theta = 1) -> init with row-0 coefficients.
        #pragma unroll
        for (int m = 0; m < 4; m++) {
            unsigned long long c = C4[m];
            unsigned clo = (unsigned)c, chi = (unsigned)(c >> 32);
            acc0[2*m] = clo; acc0[2*m+1] = chi;
            acc1[2*m] = clo; acc1[2*m+1] = chi;
            acc2[2*m] = clo; acc2[2*m+1] = chi;
        }

        // Row update: 4 scalar LDS.64 + 3 CVT + 24 HFMA2.
        #define ROW_OP(l, t0, t1, t2) do {                                     \
            unsigned p0, p1, p2;                                               \
            { float _a = (t0); CVT2(p0, _a, _a); }                             \
            { float _b = (t1); CVT2(p1, _b, _b); }                             \
            { float _c = (t2); CVT2(p2, _c, _c); }                             \
            const unsigned long long* row_ = &C4[(l) * 4];                     \
            _Pragma("unroll")                                                  \
            for (int m = 0; m < 4; m++) {                                      \
                unsigned long long cc = row_[m];                               \
                unsigned clo = (unsigned)cc, chi = (unsigned)(cc >> 32);       \
                acc0[2*m]   = hfma2(p0, clo, acc0[2*m]);                       \
                acc0[2*m+1] = hfma2(p0, chi, acc0[2*m+1]);                     \
                acc1[2*m]   = hfma2(p1, clo, acc1[2*m]);                       \
                acc1[2*m+1] = hfma2(p1, chi, acc1[2*m+1]);                     \
                acc2[2*m]   = hfma2(p2, clo, acc2[2*m]);                       \
                acc2[2*m+1] = hfma2(p2, chi, acc2[2*m+1]);                     \
            }                                                                  \
        } while (0)

        // Linear terms: rows 1..16
        #pragma unroll 4
        for (int i = 0; i < LATENT; i++) {
            ROW_OP(1 + i, z0[i], z1[i], z2[i]);
        }

        // Quadratic terms: rows 17..152, triu(i<=j) row-major (runtime loops
        // on purpose — full unroll spills).
        {
            int l = 1 + LATENT;
            for (int i = 0; i < LATENT; i++) {
                float a = z0[i], b = z1[i], c3 = z2[i];
                for (int j = i; j < LATENT; j++) {
                    ROW_OP(l, a * z0[j], b * z1[j], c3 * z2[j]);
                    l++;
                }
            }
        }

        // Sine terms: rows 153..168
        #pragma unroll 4
        for (int i = 0; i < LATENT; i++) {
            ROW_OP(153 + i, __sinf(z0[i]), __sinf(z1[i]), __sinf(z2[i]));
        }
        #undef ROW_OP

        // Euler update: z += dz * DT (dz from bf16x2 halves via bit tricks)
        #pragma unroll
        for (int q = 0; q < 8; q++) {
            z0[2*q+0] = fmaf(bf16lo_f(acc0[q]), DT_F, z0[2*q+0]);
            z0[2*q+1] = fmaf(bf16hi_f(acc0[q]), DT_F, z0[2*q+1]);
            z1[2*q+0] = fmaf(bf16lo_f(acc1[q]), DT_F, z1[2*q+0]);
            z1[2*q+1] = fmaf(bf16hi_f(acc1[q]), DT_F, z1[2*q+1]);
            z2[2*q+0] = fmaf(bf16lo_f(acc2[q]), DT_F, z2[2*q+0]);
            z2[2*q+1] = fmaf(bf16hi_f(acc2[q]), DT_F, z2[2*q+1]);
        }
    }

    // Store out[n][r][0:16]
    {
        float4* po = reinterpret_cast<float4*>(out + ((size_t)n0 * NREP + r) * LATENT);
        #pragma unroll
        for (int k = 0; k < 4; k++)
            po[k] = make_float4(z0[4*k+0], z0[4*k+1], z0[4*k+2], z0[4*k+3]);
        if (v1) {
            float4* p1 = reinterpret_cast<float4*>(out + ((size_t)n1 * NREP + r) * LATENT);
            #pragma unroll
            for (int k = 0; k < 4; k++)
                p1[k] = make_float4(z1[4*k+0], z1[4*k+1], z1[4*k+2], z1[4*k+3]);
        }
        if (v2) {
            float4* p2 = reinterpret_cast<float4*>(out + ((size_t)n2 * NREP + r) * LATENT);
            #pragma unroll
            for (int k = 0; k < 4; k++)
                p2[k] = make_float4(z2[4*k+0], z2[4*k+1], z2[4*k+2], z2[4*k+3]);
        }
    }
}

extern "C" void kernel_launch(void* const* d_in, const int* in_sizes, int n_in,
                              void* d_out, int out_size)
{
    const float* h_t   = (const float*)d_in[0];   // [50000, 16]
    const float* coeff = (const float*)d_in[1];   // [10, 169, 16]
    const float* mask  = (const float*)d_in[2];   // [10, 169, 16]
    float* out = (float*)d_out;                   // [50000, 10, 16]

    int n_total = in_sizes[0] / LATENT;
    int blocks_x = (n_total + 383) / 384;         // 384 samples per block
    dim3 grid((unsigned)blocks_x, NREP, 1);
    sindy_shred_kernel<<<grid, 128>>>(h_t, coeff, mask, out, n_total);
}

// round 9
// speedup vs baseline: 3.0426x; 1.0506x over previous
#include <cuda_runtime.h>
#include <cuda_bf16.h>

#define LATENT   16
#define NREP     10
#define NSTEPS   10
#define NLIB     169
#define DT_F     0.01f

#define SEL_LO 0x1010u   // duplicate low bf16 half
#define SEL_HI 0x3232u   // duplicate high bf16 half

__device__ __forceinline__ unsigned long long pack2u(unsigned lo, unsigned hi) {
    unsigned long long r;
    asm("mov.b64 %0, {%1, %2};" : "=l"(r) : "r"(lo), "r"(hi));
    return r;
}
// bf16x2 FMA (fma pipe, 2 MACs/instr)
__device__ __forceinline__ unsigned hfma2(unsigned a, unsigned b, unsigned c) {
    unsigned d;
    asm("fma.rn.bf16x2 %0, %1, %2, %3;" : "=r"(d) : "r"(a), "r"(b), "r"(c));
    return d;
}
// bf16x2 multiply (fma pipe) — two thetas per instruction
__device__ __forceinline__ unsigned hmul2(unsigned a, unsigned b) {
    unsigned d;
    asm("mul.rn.bf16x2 %0, %1, %2;" : "=r"(d) : "r"(a), "r"(b));
    return d;
}
// splat one bf16 half across both lanes (ALU pipe)
__device__ __forceinline__ unsigned prmt(unsigned a, unsigned sel) {
    unsigned d;
    asm("prmt.b32 %0, %1, %1, %2;" : "=r"(d) : "r"(a), "r"(sel));
    return d;
}
// pack (lo, hi) f32 -> bf16x2  (PTX cvt puts first operand in HIGH half)
#define CVT2(dst, lo, hi) \
    asm("cvt.rn.bf16x2.f32 %0, %1, %2;" : "=r"(dst) : "f"(hi), "f"(lo))

__device__ __forceinline__ float bf16lo_f(unsigned v) { return __uint_as_float(v << 16); }
__device__ __forceinline__ float bf16hi_f(unsigned v) { return __uint_as_float(v & 0xFFFF0000u); }

// THREE samples/thread, bf16x2 HFMA2 contraction. Theta generation is moved
// OFF the fma pipe: z packed to bf16x2 once per step; quadratic thetas via
// mul.bf16x2 (one instr = two thetas); all theta splats via PRMT (ALU pipe).
// ROW_OP is pure: 4x LDS.64 + 24x HFMA2. fma pipe carries only the
// irreducible MACs (+72 HMUL2) per sample-step.
__global__ __launch_bounds__(128, 3)
void sindy_shred_kernel(const float* __restrict__ h_t,
                        const float* __restrict__ coeff,
                        const float* __restrict__ mask,
                        float* __restrict__ out,
                        int n_total)
{
    // C4[row*4 + m] = u64 with coeffs d=4m..4m+3 as two bf16x2 pairs
    __shared__ __align__(16) unsigned long long C4[NLIB * 4];

    const int r = blockIdx.y;
    {
        const float* cr = coeff + (size_t)r * NLIB * LATENT;
        const float* mr = mask  + (size_t)r * NLIB * LATENT;
        for (int idx = threadIdx.x; idx < NLIB * 4; idx += blockDim.x) {
            int base = idx * 4;
            float c0 = cr[base + 0] * mr[base + 0];
            float c1 = cr[base + 1] * mr[base + 1];
            float c2 = cr[base + 2] * mr[base + 2];
            float c3 = cr[base + 3] * mr[base + 3];
            unsigned plo, phi;
            CVT2(plo, c0, c1);
            CVT2(phi, c2, c3);
            C4[idx] = pack2u(plo, phi);
        }
    }
    __syncthreads();

    const int n0 = blockIdx.x * 384 + threadIdx.x;   // 3 samples/thread
    const int n1 = n0 + 128;
    const int n2 = n0 + 256;
    const bool v1 = (n1 < n_total);
    const bool v2 = (n2 < n_total);
    if (n0 >= n_total) return;

    float z0[LATENT], z1[LATENT], z2[LATENT];
    {
        const float4* p0 = reinterpret_cast<const float4*>(h_t + (size_t)n0 * LATENT);
        #pragma unroll
        for (int k = 0; k < 4; k++) {
            float4 v = p0[k];
            z0[4*k+0] = v.x; z0[4*k+1] = v.y; z0[4*k+2] = v.z; z0[4*k+3] = v.w;
        }
        if (v1) {
            const float4* p1 = reinterpret_cast<const float4*>(h_t + (size_t)n1 * LATENT);
            #pragma unroll
            for (int k = 0; k < 4; k++) {
                float4 v = p1[k];
                z1[4*k+0] = v.x; z1[4*k+1] = v.y; z1[4*k+2] = v.z; z1[4*k+3] = v.w;
            }
        } else {
            #pragma unroll
            for (int k = 0; k < LATENT; k++) z1[k] = 0.0f;
        }
        if (v2) {
            const float4* p2 = reinterpret_cast<const float4*>(h_t + (size_t)n2 * LATENT);
            #pragma unroll
            for (int k = 0; k < 4; k++) {
                float4 v = p2[k];
                z2[4*k+0] = v.x; z2[4*k+1] = v.y; z2[4*k+2] = v.z; z2[4*k+3] = v.w;
            }
        } else {
            #pragma unroll
            for (int k = 0; k < LATENT; k++) z2[k] = 0.0f;
        }
    }

    for (int step = 0; step < NSTEPS; step++) {
        // Pack z into bf16x2: zp[m] = (z[2m], z[2m+1])
        unsigned zp0[8], zp1[8], zp2[8];
        #pragma unroll
        for (int m = 0; m < 8; m++) {
            CVT2(zp0[m], z0[2*m], z0[2*m+1]);
            CVT2(zp1[m], z1[2*m], z1[2*m+1]);
            CVT2(zp2[m], z2[2*m], z2[2*m+1]);
        }

        unsigned acc0[8], acc1[8], acc2[8];
        #pragma unroll
        for (int m = 0; m < 4; m++) {
            unsigned long long c = C4[m];
            unsigned clo = (unsigned)c, chi = (unsigned)(c >> 32);
            acc0[2*m] = clo; acc0[2*m+1] = chi;
            acc1[2*m] = clo; acc1[2*m+1] = chi;
            acc2[2*m] = clo; acc2[2*m+1] = chi;
        }

        // Pure contraction row: 4x LDS.64 + 24x HFMA2 (theta pre-splatted)
        #define ROW_OP(l, t0, t1, t2) do {                                     \
            const unsigned long long* row_ = &C4[(l) * 4];                     \
            _Pragma("unroll")                                                  \
            for (int m = 0; m < 4; m++) {                                      \
                unsigned long long cc = row_[m];                               \
                unsigned clo = (unsigned)cc, chi = (unsigned)(cc >> 32);       \
                acc0[2*m]   = hfma2((t0), clo, acc0[2*m]);                     \
                acc0[2*m+1] = hfma2((t0), chi, acc0[2*m+1]);                   \
                acc1[2*m]   = hfma2((t1), clo, acc1[2*m]);                     \
                acc1[2*m+1] = hfma2((t1), chi, acc1[2*m+1]);                   \
                acc2[2*m]   = hfma2((t2), clo, acc2[2*m]);                     \
                acc2[2*m+1] = hfma2((t2), chi, acc2[2*m+1]);                   \
            }                                                                  \
        } while (0)

        // Linear rows 1..16: theta = splat(z_i) from zp halves
        {
            int l = 1;
            #pragma unroll 2
            for (int m = 0; m < 8; m++) {
                unsigned t0 = prmt(zp0[m], SEL_LO);
                unsigned t1 = prmt(zp1[m], SEL_LO);
                unsigned t2 = prmt(zp2[m], SEL_LO);
                ROW_OP(l, t0, t1, t2); l++;
                t0 = prmt(zp0[m], SEL_HI);
                t1 = prmt(zp1[m], SEL_HI);
                t2 = prmt(zp2[m], SEL_HI);
                ROW_OP(l, t0, t1, t2); l++;
            }
        }

        // Quadratic rows 17..152: pp = splat(z_i) *bf16 zp[m] gives 2 thetas
        {
            int l = 1 + LATENT;
            for (int i = 0; i < LATENT; i++) {
                unsigned sel = (i & 1) ? SEL_HI : SEL_LO;
                unsigned zi0 = prmt(zp0[i >> 1], sel);
                unsigned zi1 = prmt(zp1[i >> 1], sel);
                unsigned zi2 = prmt(zp2[i >> 1], sel);
                int m = i >> 1;
                {   // first pair block: lo theta only valid when i even
                    unsigned pp0 = hmul2(zi0, zp0[m]);
                    unsigned pp1 = hmul2(zi1, zp1[m]);
                    unsigned pp2 = hmul2(zi2, zp2[m]);
                    if (!(i & 1)) {
                        ROW_OP(l, prmt(pp0, SEL_LO), prmt(pp1, SEL_LO), prmt(pp2, SEL_LO));
                        l++;
                    }
                    ROW_OP(l, prmt(pp0, SEL_HI), prmt(pp1, SEL_HI), prmt(pp2, SEL_HI));
                    l++;
                }
                for (m = (i >> 1) + 1; m < 8; m++) {
                    unsigned pp0 = hmul2(zi0, zp0[m]);
                    unsigned pp1 = hmul2(zi1, zp1[m]);
                    unsigned pp2 = hmul2(zi2, zp2[m]);
                    ROW_OP(l, prmt(pp0, SEL_LO), prmt(pp1, SEL_LO), prmt(pp2, SEL_LO));
                    l++;
                    ROW_OP(l, prmt(pp0, SEL_HI), prmt(pp1, SEL_HI), prmt(pp2, SEL_HI));
                    l++;
                }
            }
        }

        // Sine rows 153..168: sin in fp32 (MUFU), pack, splat
        {
            unsigned sp0[8], sp1[8], sp2[8];
            #pragma unroll
            for (int m = 0; m < 8; m++) {
                CVT2(sp0[m], __sinf(z0[2*m]), __sinf(z0[2*m+1]));
                CVT2(sp1[m], __sinf(z1[2*m]), __sinf(z1[2*m+1]));
                CVT2(sp2[m], __sinf(z2[2*m]), __sinf(z2[2*m+1]));
            }
            int l = 153;
            #pragma unroll 2
            for (int m = 0; m < 8; m++) {
                unsigned t0 = prmt(sp0[m], SEL_LO);
                unsigned t1 = prmt(sp1[m], SEL_LO);
                unsigned t2 = prmt(sp2[m], SEL_LO);
                ROW_OP(l, t0, t1, t2); l++;
                t0 = prmt(sp0[m], SEL_HI);
                t1 = prmt(sp1[m], SEL_HI);
                t2 = prmt(sp2[m], SEL_HI);
                ROW_OP(l, t0, t1, t2); l++;
            }
        }
        #undef ROW_OP

        // Euler: z += dz * DT
        #pragma unroll
        for (int q = 0; q < 8; q++) {
            z0[2*q+0] = fmaf(bf16lo_f(acc0[q]), DT_F, z0[2*q+0]);
            z0[2*q+1] = fmaf(bf16hi_f(acc0[q]), DT_F, z0[2*q+1]);
            z1[2*q+0] = fmaf(bf16lo_f(acc1[q]), DT_F, z1[2*q+0]);
            z1[2*q+1] = fmaf(bf16hi_f(acc1[q]), DT_F, z1[2*q+1]);
            z2[2*q+0] = fmaf(bf16lo_f(acc2[q]), DT_F, z2[2*q+0]);
            z2[2*q+1] = fmaf(bf16hi_f(acc2[q]), DT_F, z2[2*q+1]);
        }
    }

    {
        float4* po = reinterpret_cast<float4*>(out + ((size_t)n0 * NREP + r) * LATENT);
        #pragma unroll
        for (int k = 0; k < 4; k++)
            po[k] = make_float4(z0[4*k+0], z0[4*k+1], z0[4*k+2], z0[4*k+3]);
        if (v1) {
            float4* p1 = reinterpret_cast<float4*>(out + ((size_t)n1 * NREP + r) * LATENT);
            #pragma unroll
            for (int k = 0; k < 4; k++)
                p1[k] = make_float4(z1[4*k+0], z1[4*k+1], z1[4*k+2], z1[4*k+3]);
        }
        if (v2) {
            float4* p2 = reinterpret_cast<float4*>(out + ((size_t)n2 * NREP + r) * LATENT);
            #pragma unroll
            for (int k = 0; k < 4; k++)
                p2[k] = make_float4(z2[4*k+0], z2[4*k+1], z2[4*k+2], z2[4*k+3]);
        }
    }
}

extern "C" void kernel_launch(void* const* d_in, const int* in_sizes, int n_in,
                              void* d_out, int out_size)
{
    const float* h_t   = (const float*)d_in[0];   // [50000, 16]
    const float* coeff = (const float*)d_in[1];   // [10, 169, 16]
    const float* mask  = (const float*)d_in[2];   // [10, 169, 16]
    float* out = (float*)d_out;                   // [50000, 10, 16]

    int n_total = in_sizes[0] / LATENT;
    int blocks_x = (n_total + 383) / 384;
    dim3 grid((unsigned)blocks_x, NREP, 1);
    sindy_shred_kernel<<<grid, 128>>>(h_t, coeff, mask, out, n_total);
}

// round 10
// speedup vs baseline: 3.0944x; 1.0170x over previous
#include <cuda_runtime.h>
#include <cuda_bf16.h>

#define LATENT   16
#define NREP     10
#define NSTEPS   10
#define NLIB     169
#define DT_F     0.01f

#define SEL_LO 0x1010u   // duplicate low bf16 half
#define SEL_HI 0x3232u   // duplicate high bf16 half

__device__ __forceinline__ unsigned long long pack2u(unsigned lo, unsigned hi) {
    unsigned long long r;
    asm("mov.b64 %0, {%1, %2};" : "=l"(r) : "r"(lo), "r"(hi));
    return r;
}
__device__ __forceinline__ unsigned hfma2(unsigned a, unsigned b, unsigned c) {
    unsigned d;
    asm("fma.rn.bf16x2 %0, %1, %2, %3;" : "=r"(d) : "r"(a), "r"(b), "r"(c));
    return d;
}
__device__ __forceinline__ unsigned hmul2(unsigned a, unsigned b) {
    unsigned d;
    asm("mul.rn.bf16x2 %0, %1, %2;" : "=r"(d) : "r"(a), "r"(b));
    return d;
}
__device__ __forceinline__ unsigned prmt(unsigned a, unsigned sel) {
    unsigned d;
    asm("prmt.b32 %0, %1, %1, %2;" : "=r"(d) : "r"(a), "r"(sel));
    return d;
}
#define CVT2(dst, lo, hi) \
    asm("cvt.rn.bf16x2.f32 %0, %1, %2;" : "=r"(dst) : "f"(hi), "f"(lo))

__device__ __forceinline__ float bf16lo_f(unsigned v) { return __uint_as_float(v << 16); }
__device__ __forceinline__ float bf16hi_f(unsigned v) { return __uint_as_float(v & 0xFFFF0000u); }

// THREE samples/thread, bf16x2 HFMA2 contraction (fma pipe at its floor).
// R9 change: sine thetas computed INLINE (no sp[] arrays -> ~24 fewer live
// regs) and launch_bounds(128,4) -> 4 blocks/SM (16 warps) for latency hiding.
__global__ __launch_bounds__(128, 4)
void sindy_shred_kernel(const float* __restrict__ h_t,
                        const float* __restrict__ coeff,
                        const float* __restrict__ mask,
                        float* __restrict__ out,
                        int n_total)
{
    // C4[row*4 + m] = u64 with coeffs d=4m..4m+3 as two bf16x2 pairs
    __shared__ __align__(16) unsigned long long C4[NLIB * 4];

    const int r = blockIdx.y;
    {
        const float* cr = coeff + (size_t)r * NLIB * LATENT;
        const float* mr = mask  + (size_t)r * NLIB * LATENT;
        for (int idx = threadIdx.x; idx < NLIB * 4; idx += blockDim.x) {
            int base = idx * 4;
            float c0 = cr[base + 0] * mr[base + 0];
            float c1 = cr[base + 1] * mr[base + 1];
            float c2 = cr[base + 2] * mr[base + 2];
            float c3 = cr[base + 3] * mr[base + 3];
            unsigned plo, phi;
            CVT2(plo, c0, c1);
            CVT2(phi, c2, c3);
            C4[idx] = pack2u(plo, phi);
        }
    }
    __syncthreads();

    const int n0 = blockIdx.x * 384 + threadIdx.x;   // 3 samples/thread
    const int n1 = n0 + 128;
    const int n2 = n0 + 256;
    const bool v1 = (n1 < n_total);
    const bool v2 = (n2 < n_total);
    if (n0 >= n_total) return;

    float z0[LATENT], z1[LATENT], z2[LATENT];
    {
        const float4* p0 = reinterpret_cast<const float4*>(h_t + (size_t)n0 * LATENT);
        #pragma unroll
        for (int k = 0; k < 4; k++) {
            float4 v = p0[k];
            z0[4*k+0] = v.x; z0[4*k+1] = v.y; z0[4*k+2] = v.z; z0[4*k+3] = v.w;
        }
        if (v1) {
            const float4* p1 = reinterpret_cast<const float4*>(h_t + (size_t)n1 * LATENT);
            #pragma unroll
            for (int k = 0; k < 4; k++) {
                float4 v = p1[k];
                z1[4*k+0] = v.x; z1[4*k+1] = v.y; z1[4*k+2] = v.z; z1[4*k+3] = v.w;
            }
        } else {
            #pragma unroll
            for (int k = 0; k < LATENT; k++) z1[k] = 0.0f;
        }
        if (v2) {
            const float4* p2 = reinterpret_cast<const float4*>(h_t + (size_t)n2 * LATENT);
            #pragma unroll
            for (int k = 0; k < 4; k++) {
                float4 v = p2[k];
                z2[4*k+0] = v.x; z2[4*k+1] = v.y; z2[4*k+2] = v.z; z2[4*k+3] = v.w;
            }
        } else {
            #pragma unroll
            for (int k = 0; k < LATENT; k++) z2[k] = 0.0f;
        }
    }

    for (int step = 0; step < NSTEPS; step++) {
        // Pack z into bf16x2: zp[m] = (z[2m], z[2m+1])
        unsigned zp0[8], zp1[8], zp2[8];
        #pragma unroll
        for (int m = 0; m < 8; m++) {
            CVT2(zp0[m], z0[2*m], z0[2*m+1]);
            CVT2(zp1[m], z1[2*m], z1[2*m+1]);
            CVT2(zp2[m], z2[2*m], z2[2*m+1]);
        }

        unsigned acc0[8], acc1[8], acc2[8];
        #pragma unroll
        for (int m = 0; m < 4; m++) {
            unsigned long long c = C4[m];
            unsigned clo = (unsigned)c, chi = (unsigned)(c >> 32);
            acc0[2*m] = clo; acc0[2*m+1] = chi;
            acc1[2*m] = clo; acc1[2*m+1] = chi;
            acc2[2*m] = clo; acc2[2*m+1] = chi;
        }

        // Pure contraction row: 4x LDS.64 + 24x HFMA2 (theta pre-splatted)
        #define ROW_OP(l, t0, t1, t2) do {                                     \
            const unsigned long long* row_ = &C4[(l) * 4];                     \
            _Pragma("unroll")                                                  \
            for (int m = 0; m < 4; m++) {                                      \
                unsigned long long cc = row_[m];                               \
                unsigned clo = (unsigned)cc, chi = (unsigned)(cc >> 32);       \
                acc0[2*m]   = hfma2((t0), clo, acc0[2*m]);                     \
                acc0[2*m+1] = hfma2((t0), chi, acc0[2*m+1]);                   \
                acc1[2*m]   = hfma2((t1), clo, acc1[2*m]);                     \
                acc1[2*m+1] = hfma2((t1), chi, acc1[2*m+1]);                   \
                acc2[2*m]   = hfma2((t2), clo, acc2[2*m]);                     \
                acc2[2*m+1] = hfma2((t2), chi, acc2[2*m+1]);                   \
            }                                                                  \
        } while (0)

        // Linear rows 1..16
        {
            int l = 1;
            #pragma unroll 2
            for (int m = 0; m < 8; m++) {
                unsigned t0 = prmt(zp0[m], SEL_LO);
                unsigned t1 = prmt(zp1[m], SEL_LO);
                unsigned t2 = prmt(zp2[m], SEL_LO);
                ROW_OP(l, t0, t1, t2); l++;
                t0 = prmt(zp0[m], SEL_HI);
                t1 = prmt(zp1[m], SEL_HI);
                t2 = prmt(zp2[m], SEL_HI);
                ROW_OP(l, t0, t1, t2); l++;
            }
        }

        // Quadratic rows 17..152: pp = splat(z_i) *bf16 zp[m] -> 2 thetas
        {
            int l = 1 + LATENT;
            for (int i = 0; i < LATENT; i++) {
                unsigned sel = (i & 1) ? SEL_HI : SEL_LO;
                unsigned zi0 = prmt(zp0[i >> 1], sel);
                unsigned zi1 = prmt(zp1[i >> 1], sel);
                unsigned zi2 = prmt(zp2[i >> 1], sel);
                int m = i >> 1;
                {
                    unsigned pp0 = hmul2(zi0, zp0[m]);
                    unsigned pp1 = hmul2(zi1, zp1[m]);
                    unsigned pp2 = hmul2(zi2, zp2[m]);
                    if (!(i & 1)) {
                        ROW_OP(l, prmt(pp0, SEL_LO), prmt(pp1, SEL_LO), prmt(pp2, SEL_LO));
                        l++;
                    }
                    ROW_OP(l, prmt(pp0, SEL_HI), prmt(pp1, SEL_HI), prmt(pp2, SEL_HI));
                    l++;
                }
                for (m = (i >> 1) + 1; m < 8; m++) {
                    unsigned pp0 = hmul2(zi0, zp0[m]);
                    unsigned pp1 = hmul2(zi1, zp1[m]);
                    unsigned pp2 = hmul2(zi2, zp2[m]);
                    ROW_OP(l, prmt(pp0, SEL_LO), prmt(pp1, SEL_LO), prmt(pp2, SEL_LO));
                    l++;
                    ROW_OP(l, prmt(pp0, SEL_HI), prmt(pp1, SEL_HI), prmt(pp2, SEL_HI));
                    l++;
                }
            }
        }

        // Sine rows 153..168: computed INLINE per pair (no persistent arrays)
        {
            int l = 153;
            #pragma unroll 2
            for (int m = 0; m < 8; m++) {
                unsigned s0, s1, s2;
                CVT2(s0, __sinf(z0[2*m]), __sinf(z0[2*m+1]));
                CVT2(s1, __sinf(z1[2*m]), __sinf(z1[2*m+1]));
                CVT2(s2, __sinf(z2[2*m]), __sinf(z2[2*m+1]));
                ROW_OP(l, prmt(s0, SEL_LO), prmt(s1, SEL_LO), prmt(s2, SEL_LO));
                l++;
                ROW_OP(l, prmt(s0, SEL_HI), prmt(s1, SEL_HI), prmt(s2, SEL_HI));
                l++;
            }
        }
        #undef ROW_OP

        // Euler: z += dz * DT
        #pragma unroll
        for (int q = 0; q < 8; q++) {
            z0[2*q+0] = fmaf(bf16lo_f(acc0[q]), DT_F, z0[2*q+0]);
            z0[2*q+1] = fmaf(bf16hi_f(acc0[q]), DT_F, z0[2*q+1]);
            z1[2*q+0] = fmaf(bf16lo_f(acc1[q]), DT_F, z1[2*q+0]);
            z1[2*q+1] = fmaf(bf16hi_f(acc1[q]), DT_F, z1[2*q+1]);
            z2[2*q+0] = fmaf(bf16lo_f(acc2[q]), DT_F, z2[2*q+0]);
            z2[2*q+1] = fmaf(bf16hi_f(acc2[q]), DT_F, z2[2*q+1]);
        }
    }

    {
        float4* po = reinterpret_cast<float4*>(out + ((size_t)n0 * NREP + r) * LATENT);
        #pragma unroll
        for (int k = 0; k < 4; k++)
            po[k] = make_float4(z0[4*k+0], z0[4*k+1], z0[4*k+2], z0[4*k+3]);
        if (v1) {
            float4* p1 = reinterpret_cast<float4*>(out + ((size_t)n1 * NREP + r) * LATENT);
            #pragma unroll
            for (int k = 0; k < 4; k++)
                p1[k] = make_float4(z1[4*k+0], z1[4*k+1], z1[4*k+2], z1[4*k+3]);
        }
        if (v2) {
            float4* p2 = reinterpret_cast<float4*>(out + ((size_t)n2 * NREP + r) * LATENT);
            #pragma unroll
            for (int k = 0; k < 4; k++)
                p2[k] = make_float4(z2[4*k+0], z2[4*k+1], z2[4*k+2], z2[4*k+3]);
        }
    }
}

extern "C" void kernel_launch(void* const* d_in, const int* in_sizes, int n_in,
                              void* d_out, int out_size)
{
    const float* h_t   = (const float*)d_in[0];   // [50000, 16]
    const float* coeff = (const float*)d_in[1];   // [10, 169, 16]
    const float* mask  = (const float*)d_in[2];   // [10, 169, 16]
    float* out = (float*)d_out;                   // [50000, 10, 16]

    int n_total = in_sizes[0] / LATENT;
    int blocks_x = (n_total + 383) / 384;
    dim3 grid((unsigned)blocks_x, NREP, 1);
    sindy_shred_kernel<<<grid, 128>>>(h_t, coeff, mask, out, n_total);
}